// round 8
// baseline (speedup 1.0000x reference)
#include <cuda_runtime.h>
#include <cuda_fp16.h>

typedef unsigned long long u64;

// Problem dims (fixed by reference)
#define UDIM 400
#define VDIM 400
#define MDIM 4
#define VPAD (VDIM + 1)                     // compact table: dup column j=0 at jp=400
#define NTEX  (MDIM * UDIM * VDIM)          // 640,000 blocks
#define NTEXP (MDIM * UDIM * VPAD)          // 641,600 compact records

// Stage-1 compact fp16 table: per texel one 32B record (16 halves):
// [W00..W22 row-major (9), B0,B1,B2 (3), pad(4)]. 20.5 MB.
__device__ __align__(32) unsigned g_tbl[(size_t)NTEXP * 8];

// Stage-2 2x2 block table: per texel (m,i,j) one 96B record = all 4 bilinear
// corners in fp16, corner c = i_sel*2 + j_sel at halves 12c..12c+11.
// stride 96 = 3*32 -> every record 32B-aligned -> 3x LDG.256. 61.4 MB,
// held in L2 via evict_last policy.
__device__ __align__(32) unsigned g_blk[(size_t)NTEX * 24];

// ---------------- PTX helpers ----------------
__device__ __forceinline__ u64 make_policy_evict_last() {
    u64 p;
    asm("createpolicy.fractional.L2::evict_last.b64 %0, 1.0;" : "=l"(p));
    return p;
}
__device__ __forceinline__ u64 make_policy_evict_first() {
    u64 p;
    asm("createpolicy.fractional.L2::evict_first.b64 %0, 1.0;" : "=l"(p));
    return p;
}
__device__ __forceinline__ void ldg256_hint(const void* p, u64 pol, unsigned r[8]) {
    asm("ld.global.nc.L2::cache_hint.v8.b32 {%0,%1,%2,%3,%4,%5,%6,%7}, [%8], %9;"
        : "=r"(r[0]), "=r"(r[1]), "=r"(r[2]), "=r"(r[3]),
          "=r"(r[4]), "=r"(r[5]), "=r"(r[6]), "=r"(r[7])
        : "l"(p), "l"(pol));
}
__device__ __forceinline__ void stg128_hint(void* p, u64 pol,
                                            unsigned a, unsigned b, unsigned c, unsigned d) {
    asm("st.global.L2::cache_hint.v4.b32 [%0], {%1,%2,%3,%4}, %5;"
        :: "l"(p), "r"(a), "r"(b), "r"(c), "r"(d), "l"(pol) : "memory");
}
__device__ __forceinline__ float ldf_hint(const float* p, u64 pol) {
    float v;
    asm("ld.global.L2::cache_hint.f32 %0, [%1], %2;" : "=f"(v) : "l"(p), "l"(pol));
    return v;
}
__device__ __forceinline__ int ldi_hint(const int* p, u64 pol) {
    int v;
    asm("ld.global.L2::cache_hint.b32 %0, [%1], %2;" : "=r"(v) : "l"(p), "l"(pol));
    return v;
}
__device__ __forceinline__ void stf_hint(float* p, float v, u64 pol) {
    asm("st.global.L2::cache_hint.f32 [%0], %1, %2;" :: "l"(p), "f"(v), "l"(pol) : "memory");
}

// ---------------- Stage 1: compact fp16 convert (proven ~10us) ----------------
__global__ __launch_bounds__(256) void pack_kernel(
    const float* __restrict__ m_param,
    const float* __restrict__ b_param)
{
    int t = blockIdx.x * blockDim.x + threadIdx.x;
    if (t >= NTEXP) return;
    int m  = t / (UDIM * VPAD);
    int r  = t % (UDIM * VPAD);
    int i  = r / VPAD;
    int jp = r % VPAD;
    int j  = (jp == VDIM) ? 0 : jp;          // padded column duplicates j=0
    size_t src = (size_t)(m * UDIM + i) * VDIM + j;

    const float* w = m_param + src * 9;
    const float* b = b_param + src * 3;

    __align__(32) __half h[16];
    #pragma unroll
    for (int k = 0; k < 9; k++) h[k] = __float2half_rn(w[k]);
    #pragma unroll
    for (int k = 0; k < 3; k++) h[9 + k] = __float2half_rn(b[k]);
    h[12] = h[13] = h[14] = h[15] = __half(0.0f);

    const uint4* s = reinterpret_cast<const uint4*>(h);
    uint4* dst = reinterpret_cast<uint4*>(g_tbl + (size_t)t * 8);
    dst[0] = s[0];
    dst[1] = s[1];
}

// ---------------- Stage 2: assemble 96B 2x2 blocks ----------------
__global__ __launch_bounds__(256) void assemble_kernel() {
    int t = blockIdx.x * blockDim.x + threadIdx.x;
    if (t >= NTEX) return;
    int m = t / (UDIM * VDIM);
    int r = t % (UDIM * VDIM);
    int i = r / VDIM;
    int j = r % VDIM;
    int i2 = i + 1; if (i2 == UDIM) i2 = 0;  // i wrap; j wrap via padded column

    u64 pol_last = make_policy_evict_last();

    size_t recA = (size_t)(m * UDIM + i ) * VPAD + j;   // (i, j) / (i, j+1)
    size_t recB = (size_t)(m * UDIM + i2) * VPAD + j;   // (i2, j) / (i2, j+1)

    unsigned a1[8], a2[8], b1[8], b2[8];
    const unsigned* tb = g_tbl;
    ldg256_hint(tb + recA * 8,     pol_last, a1);   // corner 0: (i, j)
    ldg256_hint(tb + recA * 8 + 8, pol_last, a2);   // corner 1: (i, j+1)
    ldg256_hint(tb + recB * 8,     pol_last, b1);   // corner 2: (i2, j)
    ldg256_hint(tb + recB * 8 + 8, pol_last, b2);   // corner 3: (i2, j+1)

    unsigned* dst = g_blk + (size_t)t * 24;
    stg128_hint(dst +  0, pol_last, a1[0], a1[1], a1[2], a1[3]);
    stg128_hint(dst +  4, pol_last, a1[4], a1[5], a2[0], a2[1]);
    stg128_hint(dst +  8, pol_last, a2[2], a2[3], a2[4], a2[5]);
    stg128_hint(dst + 12, pol_last, b1[0], b1[1], b1[2], b1[3]);
    stg128_hint(dst + 16, pol_last, b1[4], b1[5], b2[0], b2[1]);
    stg128_hint(dst + 20, pol_last, b2[2], b2[3], b2[4], b2[5]);
}

// ---------------- interp: 3x LDG.256 per point ----------------
__global__ __launch_bounds__(256) void interp_kernel(
    const float* __restrict__ x,
    const int*   __restrict__ m,
    const float* __restrict__ u,
    const float* __restrict__ v,
    float* __restrict__ out,
    int N)
{
    int tid = blockIdx.x * blockDim.x + threadIdx.x;
    if (tid >= N) return;

    u64 pol_last  = make_policy_evict_last();
    u64 pol_first = make_policy_evict_first();

    // --- index math (mirrors reference exactly) ---
    float iu = ldf_hint(u + tid, pol_first) * (float)UDIM;
    float iv = ldf_hint(v + tid, pol_first) * (float)VDIM;
    if (iu == (float)UDIM) iu = (float)(UDIM - 1);
    if (iv == (float)VDIM) iv = (float)(VDIM - 1);

    float i1f = floorf(iu);
    float j1f = floorf(iv);
    int i1 = (int)i1f;
    int j1 = (int)j1f;
    float ir = iu - i1f;
    float jr = iv - j1f;

    int mm = ldi_hint(m + tid, pol_first);
    size_t blk = (size_t)(mm * UDIM + i1) * VDIM + j1;

    // --- one 96B block read: 3x LDG.256, evict_last (stay in L2) ---
    const unsigned* p = g_blk + blk * 24;
    unsigned uu[24];
    ldg256_hint(p,      pol_last, uu +  0);
    ldg256_hint(p +  8, pol_last, uu +  8);
    ldg256_hint(p + 16, pol_last, uu + 16);

    // weights, corner order c = i_sel*2 + j_sel
    float wgt[4];
    wgt[0] = (1.0f - ir) * (1.0f - jr);   // (i1, j1)
    wgt[1] = (1.0f - ir) * jr;            // (i1, j2)
    wgt[2] = ir * (1.0f - jr);            // (i2, j1)
    wgt[3] = ir * jr;                     // (i2, j2)

    // blend 4 corners in fp32; corner c = half2 slots 6c..6c+5
    float2 acc[6];
    #pragma unroll
    for (int s = 0; s < 6; s++) acc[s] = make_float2(0.f, 0.f);

    #pragma unroll
    for (int c = 0; c < 4; c++) {
        float wc = wgt[c];
        #pragma unroll
        for (int s = 0; s < 6; s++) {
            __half2 hv = *reinterpret_cast<const __half2*>(&uu[c * 6 + s]);
            float2 f = __half22float2(hv);
            acc[s].x = fmaf(wc, f.x, acc[s].x);
            acc[s].y = fmaf(wc, f.y, acc[s].y);
        }
    }
    // acc layout: [0]=(W00,W01) [1]=(W02,W10) [2]=(W11,W12)
    //             [3]=(W20,W21) [4]=(W22,B0)  [5]=(B1,B2)

    float x0 = ldf_hint(x + 3 * tid + 0, pol_first);
    float x1 = ldf_hint(x + 3 * tid + 1, pol_first);
    float x2 = ldf_hint(x + 3 * tid + 2, pol_first);

    // out_j = sum_i x_i * W[i][j] + B[j]
    float o0 = fmaf(x0, acc[0].x, fmaf(x1, acc[1].y, fmaf(x2, acc[3].x, acc[4].y)));
    float o1 = fmaf(x0, acc[0].y, fmaf(x1, acc[2].x, fmaf(x2, acc[3].y, acc[5].x)));
    float o2 = fmaf(x0, acc[1].x, fmaf(x1, acc[2].y, fmaf(x2, acc[4].x, acc[5].y)));
    stf_hint(out + 3 * tid + 0, o0, pol_first);
    stf_hint(out + 3 * tid + 1, o1, pol_first);
    stf_hint(out + 3 * tid + 2, o2, pol_first);
}

extern "C" void kernel_launch(void* const* d_in, const int* in_sizes, int n_in,
                              void* d_out, int out_size) {
    const float* x       = (const float*)d_in[0];   // [N,3]
    const int*   m       = (const int*)  d_in[1];   // [N]
    const float* u       = (const float*)d_in[2];   // [N]
    const float* v       = (const float*)d_in[3];   // [N]
    const float* m_param = (const float*)d_in[4];   // [M,U*V,3,3]
    const float* b_param = (const float*)d_in[5];   // [M,U*V,1,3]
    float* out = (float*)d_out;

    int N = in_sizes[1];  // element count of m

    // Stage 1: streaming fp16 convert (compact 32B records, 20.5 MB)
    {
        int blocks = (NTEXP + 255) / 256;
        pack_kernel<<<blocks, 256>>>(m_param, b_param);
    }
    // Stage 2: assemble 96B 2x2 block records (61.4 MB, pinned via evict_last)
    {
        int blocks = (NTEX + 255) / 256;
        assemble_kernel<<<blocks, 256>>>();
    }
    // Stage 3: gather (3x LDG.256) + blend + matvec per point
    {
        int blocks = (N + 255) / 256;
        interp_kernel<<<blocks, 256>>>(x, m, u, v, out, N);
    }
}

// round 9
// speedup vs baseline: 1.1746x; 1.1746x over previous
#include <cuda_runtime.h>
#include <cuda_fp16.h>

// Problem dims (fixed by reference)
#define UDIM 400
#define VDIM 400
#define MDIM 4
#define VPAD (VDIM + 1)                    // duplicate column 0 at j=400 -> no j-wrap
#define NTEXP (MDIM * UDIM * VPAD)         // 641,600 padded texels

// Compact fp16 table: per texel one 32B record (16 halves):
// [W00..W22 row-major (9), B0,B1,B2 (3), pad (4)].
// j-contiguous with VPAD -> a (j, j+1) pair is 64B contiguous, 32B-aligned.
// Total 20.5 MB -> L2-resident.
__device__ __align__(32) unsigned g_tbl[(size_t)NTEXP * 8];

__global__ __launch_bounds__(256) void pack_kernel(
    const float* __restrict__ m_param,
    const float* __restrict__ b_param)
{
    int t = blockIdx.x * blockDim.x + threadIdx.x;
    if (t >= NTEXP) return;
    int m  = t / (UDIM * VPAD);
    int r  = t % (UDIM * VPAD);
    int i  = r / VPAD;
    int jp = r % VPAD;
    int j  = (jp == VDIM) ? 0 : jp;         // padded column duplicates j=0
    size_t src = (size_t)(m * UDIM + i) * VDIM + j;

    const float* w = m_param + src * 9;
    const float* b = b_param + src * 3;

    __align__(32) __half h[16];
    #pragma unroll
    for (int k = 0; k < 9; k++) h[k] = __float2half_rn(w[k]);
    #pragma unroll
    for (int k = 0; k < 3; k++) h[9 + k] = __float2half_rn(b[k]);
    h[12] = h[13] = h[14] = h[15] = __half(0.0f);

    const uint4* s = reinterpret_cast<const uint4*>(h);
    uint4* dst = reinterpret_cast<uint4*>(g_tbl + (size_t)t * 8);
    dst[0] = s[0];
    dst[1] = s[1];
}

__device__ __forceinline__ void ldg256(const void* p, unsigned r[8]) {
    asm("ld.global.nc.v8.b32 {%0,%1,%2,%3,%4,%5,%6,%7}, [%8];"
        : "=r"(r[0]), "=r"(r[1]), "=r"(r[2]), "=r"(r[3]),
          "=r"(r[4]), "=r"(r[5]), "=r"(r[6]), "=r"(r[7])
        : "l"(p));
}

// Compute rowA/rowB byte offsets + 4 bilinear weights for one point.
__device__ __forceinline__ void point_setup(float uu, float vv, int mm,
                                            size_t& offA, size_t& offB,
                                            float wgt[4]) {
    float iu = uu * (float)UDIM;
    float iv = vv * (float)VDIM;
    if (iu == (float)UDIM) iu = (float)(UDIM - 1);
    if (iv == (float)VDIM) iv = (float)(VDIM - 1);

    float i1f = floorf(iu);
    float j1f = floorf(iv);
    int i1 = (int)i1f;
    int j1 = (int)j1f;                       // j2 via padded column
    int i2 = i1 + 1; if (i2 == UDIM) i2 = 0; // i wraps
    float ir = iu - i1f;
    float jr = iv - j1f;

    offA = ((size_t)(mm * UDIM + i1) * VPAD + j1) * 32;
    offB = ((size_t)(mm * UDIM + i2) * VPAD + j1) * 32;

    wgt[0] = (1.0f - ir) * (1.0f - jr);   // (i1, j1)
    wgt[1] = (1.0f - ir) * jr;            // (i1, j1+1)
    wgt[2] = ir * (1.0f - jr);            // (i2, j1)
    wgt[3] = ir * jr;                     // (i2, j1+1)
}

// Blend 4 loaded corner records + matvec -> 3 outputs.
__device__ __forceinline__ void point_finish(const unsigned a1[8], const unsigned a2[8],
                                             const unsigned b1[8], const unsigned b2[8],
                                             const float wgt[4],
                                             float x0, float x1, float x2,
                                             float& o0, float& o1, float& o2) {
    // record half2 slots s=0..5:
    // [0]=(W00,W01) [1]=(W02,W10) [2]=(W11,W12) [3]=(W20,W21) [4]=(W22,B0) [5]=(B1,B2)
    float2 acc[6];
    #pragma unroll
    for (int s = 0; s < 6; s++) {
        float2 fA1 = __half22float2(*reinterpret_cast<const __half2*>(&a1[s]));
        float2 fA2 = __half22float2(*reinterpret_cast<const __half2*>(&a2[s]));
        float2 fB1 = __half22float2(*reinterpret_cast<const __half2*>(&b1[s]));
        float2 fB2 = __half22float2(*reinterpret_cast<const __half2*>(&b2[s]));
        acc[s].x = fmaf(wgt[0], fA1.x, fmaf(wgt[1], fA2.x, fmaf(wgt[2], fB1.x, wgt[3] * fB2.x)));
        acc[s].y = fmaf(wgt[0], fA1.y, fmaf(wgt[1], fA2.y, fmaf(wgt[2], fB1.y, wgt[3] * fB2.y)));
    }
    // out_j = sum_i x_i * W[i][j] + B[j]
    o0 = fmaf(x0, acc[0].x, fmaf(x1, acc[1].y, fmaf(x2, acc[3].x, acc[4].y)));
    o1 = fmaf(x0, acc[0].y, fmaf(x1, acc[2].x, fmaf(x2, acc[3].y, acc[5].x)));
    o2 = fmaf(x0, acc[1].x, fmaf(x1, acc[2].y, fmaf(x2, acc[4].x, acc[5].y)));
}

// Two points per thread: vectorized (8B) stream accesses, 8 table loads in flight.
__global__ __launch_bounds__(256) void interp_kernel(
    const float* __restrict__ x,
    const int*   __restrict__ m,
    const float* __restrict__ u,
    const float* __restrict__ v,
    float* __restrict__ out,
    int N)
{
    int t2 = blockIdx.x * blockDim.x + threadIdx.x;
    int p0 = t2 * 2;
    if (p0 >= N) return;
    bool dual = (p0 + 1 < N);

    float u0, u1, v0, v1;
    int m0, m1;
    float xv[6];
    if (dual) {
        float2 uf = reinterpret_cast<const float2*>(u)[t2];
        float2 vf = reinterpret_cast<const float2*>(v)[t2];
        int2   mi = reinterpret_cast<const int2*>(m)[t2];
        float2 xa = reinterpret_cast<const float2*>(x)[3 * t2 + 0];
        float2 xb = reinterpret_cast<const float2*>(x)[3 * t2 + 1];
        float2 xc = reinterpret_cast<const float2*>(x)[3 * t2 + 2];
        u0 = uf.x; u1 = uf.y; v0 = vf.x; v1 = vf.y; m0 = mi.x; m1 = mi.y;
        xv[0] = xa.x; xv[1] = xa.y; xv[2] = xb.x;
        xv[3] = xb.y; xv[4] = xc.x; xv[5] = xc.y;
    } else {
        u0 = u[p0]; v0 = v[p0]; m0 = m[p0];
        xv[0] = x[3 * p0]; xv[1] = x[3 * p0 + 1]; xv[2] = x[3 * p0 + 2];
        u1 = 0.f; v1 = 0.f; m1 = 0;
        xv[3] = xv[4] = xv[5] = 0.f;
    }

    size_t offA0, offB0, offA1, offB1;
    float wgt0[4], wgt1[4];
    point_setup(u0, v0, m0, offA0, offB0, wgt0);
    point_setup(u1, v1, m1, offA1, offB1, wgt1);

    const char* base = reinterpret_cast<const char*>(g_tbl);

    // Issue all 8 (or 4) table loads up front for max MLP
    unsigned a1_0[8], a2_0[8], b1_0[8], b2_0[8];
    unsigned a1_1[8], a2_1[8], b1_1[8], b2_1[8];
    ldg256(base + offA0,      a1_0);
    ldg256(base + offA0 + 32, a2_0);
    ldg256(base + offB0,      b1_0);
    ldg256(base + offB0 + 32, b2_0);
    if (dual) {
        ldg256(base + offA1,      a1_1);
        ldg256(base + offA1 + 32, a2_1);
        ldg256(base + offB1,      b1_1);
        ldg256(base + offB1 + 32, b2_1);
    }

    float o00, o01, o02;
    point_finish(a1_0, a2_0, b1_0, b2_0, wgt0, xv[0], xv[1], xv[2], o00, o01, o02);

    if (dual) {
        float o10, o11, o12;
        point_finish(a1_1, a2_1, b1_1, b2_1, wgt1, xv[3], xv[4], xv[5], o10, o11, o12);
        float2* o2p = reinterpret_cast<float2*>(out) + 3 * t2;
        o2p[0] = make_float2(o00, o01);
        o2p[1] = make_float2(o02, o10);
        o2p[2] = make_float2(o11, o12);
    } else {
        out[3 * p0 + 0] = o00;
        out[3 * p0 + 1] = o01;
        out[3 * p0 + 2] = o02;
    }
}

extern "C" void kernel_launch(void* const* d_in, const int* in_sizes, int n_in,
                              void* d_out, int out_size) {
    const float* x       = (const float*)d_in[0];   // [N,3]
    const int*   m       = (const int*)  d_in[1];   // [N]
    const float* u       = (const float*)d_in[2];   // [N]
    const float* v       = (const float*)d_in[3];   // [N]
    const float* m_param = (const float*)d_in[4];   // [M,U*V,3,3]
    const float* b_param = (const float*)d_in[5];   // [M,U*V,1,3]
    float* out = (float*)d_out;

    int N = in_sizes[1];  // element count of m

    // Stage 1: streaming convert to compact fp16 records (20.5 MB, L2-resident)
    {
        int blocks = (NTEXP + 255) / 256;
        pack_kernel<<<blocks, 256>>>(m_param, b_param);
    }
    // Stage 2: gather (4x LDG.256 per point, 2 points per thread) + blend + matvec
    {
        int npair = (N + 1) / 2;
        int blocks = (npair + 255) / 256;
        interp_kernel<<<blocks, 256>>>(x, m, u, v, out, N);
    }
}